// round 1
// baseline (speedup 1.0000x reference)
#include <cuda_runtime.h>
#include <math.h>

#define T_TOK 8192
#define DIM   1024
#define DFF   4096
#define NE    8

// -------- scratch (device globals; no allocation) --------
__device__ int   d_cnt[NE];
__device__ int   d_amax[NE];
__device__ float d_probs[NE];
__device__ int   d_tok[NE * T_TOK];   // pair id = t*2+slot
__device__ float d_gw [NE * T_TOK];
__device__ float d_H[(size_t)2 * T_TOK * DFF]; // 256 MB, indexed by pair id
__device__ float d_Y[(size_t)2 * T_TOK * DIM]; // 64 MB, indexed by pair id

// -------- zero counters (must run each launch: graph replays) --------
__global__ void zero_kernel() {
    int i = threadIdx.x;
    if (i < NE) { d_cnt[i] = 0; d_amax[i] = 0; d_probs[i] = 0.0f; }
}

// -------- gating: logits, top-2 softmax, lb-loss stats, expert lists --------
__global__ __launch_bounds__(256) void gate_kernel(
    const float* __restrict__ x, const float* __restrict__ gate_w)
{
    int t = blockIdx.x;
    __shared__ float xs[DIM];
    __shared__ float lg[NE];
    for (int i = threadIdx.x; i < DIM; i += 256) xs[i] = x[(size_t)t * DIM + i];
    __syncthreads();
    int w = threadIdx.x >> 5, lane = threadIdx.x & 31;   // 8 warps = 8 experts
    const float* gr = gate_w + w * DIM;
    float s = 0.0f;
    for (int i = lane; i < DIM; i += 32) s += xs[i] * gr[i];
    #pragma unroll
    for (int o = 16; o; o >>= 1) s += __shfl_xor_sync(0xffffffffu, s, o);
    if (lane == 0) lg[w] = s;
    __syncthreads();
    if (threadIdx.x == 0) {
        int i0 = 0;
        #pragma unroll
        for (int e = 1; e < NE; e++) if (lg[e] > lg[i0]) i0 = e;
        int i1 = -1;
        #pragma unroll
        for (int e = 0; e < NE; e++) {
            if (e == i0) continue;
            if (i1 < 0 || lg[e] > lg[i1]) i1 = e;
        }
        float v0 = lg[i0], v1 = lg[i1];
        float ee = expf(v1 - v0);
        float g0 = 1.0f / (1.0f + ee);
        float g1 = ee / (1.0f + ee);
        // full softmax for lb loss
        float mx = v0, se = 0.0f, p[NE];
        #pragma unroll
        for (int e = 0; e < NE; e++) { p[e] = expf(lg[e] - mx); se += p[e]; }
        float inv = 1.0f / se;
        #pragma unroll
        for (int e = 0; e < NE; e++) atomicAdd(&d_probs[e], p[e] * inv);
        atomicAdd(&d_amax[i0], 1);
        int pos0 = atomicAdd(&d_cnt[i0], 1);
        d_tok[i0 * T_TOK + pos0] = t * 2 + 0;
        d_gw [i0 * T_TOK + pos0] = g0;
        int pos1 = atomicAdd(&d_cnt[i1], 1);
        d_tok[i1 * T_TOK + pos1] = t * 2 + 1;
        d_gw [i1 * T_TOK + pos1] = g1;
    }
}

__device__ __forceinline__ float gelu_exact(float v) {
    return 0.5f * v * (1.0f + erff(v * 0.7071067811865475f));
}

// -------- GEMM1: H[pair, DFF] = gelu( x[tok] @ w1[e]^T + b1[e] ) --------
// NT layout: A rows K-contiguous (x), B rows K-contiguous (w1[e] is [DFF, D]).
__global__ __launch_bounds__(256) void ffn1_kernel(
    const float* __restrict__ x, const float* __restrict__ w1,
    const float* __restrict__ b1)
{
    int e  = blockIdx.z;
    int Me = d_cnt[e];
    int m0 = blockIdx.y * 64;
    if (m0 >= Me) return;
    int n0 = blockIdx.x * 64;
    const float* Bm = w1 + (size_t)e * DFF * DIM + (size_t)n0 * DIM;

    __shared__ float As[16][68];
    __shared__ float Bs[16][68];
    __shared__ int   prow[64];

    int tid = threadIdx.x;
    if (tid < 64) {
        int m = m0 + tid;
        prow[tid] = (m < Me) ? d_tok[e * T_TOK + m] : -1;
    }
    __syncthreads();

    int tx = tid & 15, ty = tid >> 4;
    int lrow = tid >> 2;
    int lk   = (tid & 3) * 4;
    float acc[4][4] = {};

    for (int k0 = 0; k0 < DIM; k0 += 16) {
        float4 av = make_float4(0.f, 0.f, 0.f, 0.f);
        int p = prow[lrow];
        if (p >= 0)
            av = *(const float4*)(x + (size_t)(p >> 1) * DIM + k0 + lk);
        As[lk + 0][lrow] = av.x; As[lk + 1][lrow] = av.y;
        As[lk + 2][lrow] = av.z; As[lk + 3][lrow] = av.w;
        float4 bv = *(const float4*)(Bm + (size_t)lrow * DIM + k0 + lk);
        Bs[lk + 0][lrow] = bv.x; Bs[lk + 1][lrow] = bv.y;
        Bs[lk + 2][lrow] = bv.z; Bs[lk + 3][lrow] = bv.w;
        __syncthreads();
        #pragma unroll
        for (int k = 0; k < 16; k++) {
            float a[4], b[4];
            #pragma unroll
            for (int i = 0; i < 4; i++) a[i] = As[k][ty * 4 + i];
            #pragma unroll
            for (int j = 0; j < 4; j++) b[j] = Bs[k][tx * 4 + j];
            #pragma unroll
            for (int i = 0; i < 4; i++)
                #pragma unroll
                for (int j = 0; j < 4; j++) acc[i][j] += a[i] * b[j];
        }
        __syncthreads();
    }
    const float* b1e = b1 + e * DFF + n0;
    #pragma unroll
    for (int i = 0; i < 4; i++) {
        int m = m0 + ty * 4 + i;
        if (m >= Me) break;
        int p = d_tok[e * T_TOK + m];
        float* dst = d_H + (size_t)p * DFF + n0;
        #pragma unroll
        for (int j = 0; j < 4; j++) {
            int n = tx * 4 + j;
            dst[n] = gelu_exact(acc[i][j] + b1e[n]);
        }
    }
}

// -------- GEMM2: Y[pair, D] = gw * ( H[pair] @ w2[e]^T + b2[e] ) --------
__global__ __launch_bounds__(256) void ffn2_kernel(
    const float* __restrict__ w2, const float* __restrict__ b2)
{
    int e  = blockIdx.z;
    int Me = d_cnt[e];
    int m0 = blockIdx.y * 64;
    if (m0 >= Me) return;
    int n0 = blockIdx.x * 64;
    const float* Bm = w2 + (size_t)e * DIM * DFF + (size_t)n0 * DFF;

    __shared__ float As[16][68];
    __shared__ float Bs[16][68];
    __shared__ int   prow[64];

    int tid = threadIdx.x;
    if (tid < 64) {
        int m = m0 + tid;
        prow[tid] = (m < Me) ? d_tok[e * T_TOK + m] : -1;
    }
    __syncthreads();

    int tx = tid & 15, ty = tid >> 4;
    int lrow = tid >> 2;
    int lk   = (tid & 3) * 4;
    float acc[4][4] = {};

    for (int k0 = 0; k0 < DFF; k0 += 16) {
        float4 av = make_float4(0.f, 0.f, 0.f, 0.f);
        int p = prow[lrow];
        if (p >= 0)
            av = *(const float4*)(d_H + (size_t)p * DFF + k0 + lk);
        As[lk + 0][lrow] = av.x; As[lk + 1][lrow] = av.y;
        As[lk + 2][lrow] = av.z; As[lk + 3][lrow] = av.w;
        float4 bv = *(const float4*)(Bm + (size_t)lrow * DFF + k0 + lk);
        Bs[lk + 0][lrow] = bv.x; Bs[lk + 1][lrow] = bv.y;
        Bs[lk + 2][lrow] = bv.z; Bs[lk + 3][lrow] = bv.w;
        __syncthreads();
        #pragma unroll
        for (int k = 0; k < 16; k++) {
            float a[4], b[4];
            #pragma unroll
            for (int i = 0; i < 4; i++) a[i] = As[k][ty * 4 + i];
            #pragma unroll
            for (int j = 0; j < 4; j++) b[j] = Bs[k][tx * 4 + j];
            #pragma unroll
            for (int i = 0; i < 4; i++)
                #pragma unroll
                for (int j = 0; j < 4; j++) acc[i][j] += a[i] * b[j];
        }
        __syncthreads();
    }
    const float* b2e = b2 + e * DIM + n0;
    #pragma unroll
    for (int i = 0; i < 4; i++) {
        int m = m0 + ty * 4 + i;
        if (m >= Me) break;
        int p  = d_tok[e * T_TOK + m];
        float g = d_gw[e * T_TOK + m];
        float* dst = d_Y + (size_t)p * DIM + n0;
        #pragma unroll
        for (int j = 0; j < 4; j++) {
            int n = tx * 4 + j;
            dst[n] = g * (acc[i][j] + b2e[n]);
        }
    }
}

// -------- combine the two expert contributions per token --------
__global__ void combine_kernel(float* __restrict__ out)
{
    size_t i = (size_t)blockIdx.x * blockDim.x + threadIdx.x; // float4 index
    size_t total = (size_t)T_TOK * DIM / 4;
    if (i >= total) return;
    size_t t = i / (DIM / 4);
    size_t d4 = i % (DIM / 4);
    const float4* y0 = (const float4*)(d_Y + (t * 2 + 0) * DIM) + d4;
    const float4* y1 = (const float4*)(d_Y + (t * 2 + 1) * DIM) + d4;
    float4 a = *y0, b = *y1;
    float4 r = make_float4(a.x + b.x, a.y + b.y, a.z + b.z, a.w + b.w);
    ((float4*)out)[i] = r;
}

// -------- load-balance loss --------
__global__ void loss_kernel(float* __restrict__ out, int out_size)
{
    if (threadIdx.x == 0 && blockIdx.x == 0) {
        float lb = 0.0f;
        const float invT = 1.0f / (float)T_TOK;
        #pragma unroll
        for (int e = 0; e < NE; e++)
            lb += ((float)d_amax[e] * invT) * (d_probs[e] * invT);
        lb *= (float)NE;
        if (out_size > T_TOK * DIM) out[T_TOK * DIM] = lb;
    }
}

extern "C" void kernel_launch(void* const* d_in, const int* in_sizes, int n_in,
                              void* d_out, int out_size)
{
    const float* x      = (const float*)d_in[0];
    const float* gate_w = (const float*)d_in[1];
    const float* w1     = (const float*)d_in[2];
    const float* b1     = (const float*)d_in[3];
    const float* w2     = (const float*)d_in[4];
    const float* b2     = (const float*)d_in[5];
    float* out = (float*)d_out;

    zero_kernel<<<1, 32>>>();
    gate_kernel<<<T_TOK, 256>>>(x, gate_w);
    ffn1_kernel<<<dim3(DFF / 64, T_TOK / 64, NE), 256>>>(x, w1, b1);
    ffn2_kernel<<<dim3(DIM / 64, T_TOK / 64, NE), 256>>>(w2, b2);
    {
        size_t total = (size_t)T_TOK * DIM / 4;
        combine_kernel<<<(unsigned)((total + 255) / 256), 256>>>(out);
    }
    loss_kernel<<<1, 32>>>(out, out_size);
}

// round 2
// speedup vs baseline: 1.9994x; 1.9994x over previous
#include <cuda_runtime.h>
#include <math.h>

#define T_TOK 8192
#define DIM   1024
#define DFF   4096
#define NE    8

// -------- scratch (device globals; no allocation) --------
__device__ int   d_cnt[NE];
__device__ int   d_amax[NE];
__device__ float d_probs[NE];
__device__ int   d_tok[NE * T_TOK];   // pair id = t*2+slot
__device__ float d_gw [NE * T_TOK];
__device__ float d_H[(size_t)2 * T_TOK * DFF]; // 256 MB, indexed by pair id
__device__ float d_Y[(size_t)2 * T_TOK * DIM]; // 64 MB, indexed by pair id

// -------- zero counters (graph replays: must run each launch) --------
__global__ void zero_kernel() {
    int i = threadIdx.x;
    if (i < NE) { d_cnt[i] = 0; d_amax[i] = 0; d_probs[i] = 0.0f; }
}

// -------- gating --------
__global__ __launch_bounds__(256) void gate_kernel(
    const float* __restrict__ x, const float* __restrict__ gate_w)
{
    int t = blockIdx.x;
    __shared__ float xs[DIM];
    __shared__ float lg[NE];
    for (int i = threadIdx.x; i < DIM; i += 256) xs[i] = x[(size_t)t * DIM + i];
    __syncthreads();
    int w = threadIdx.x >> 5, lane = threadIdx.x & 31;
    const float* gr = gate_w + w * DIM;
    float s = 0.0f;
    for (int i = lane; i < DIM; i += 32) s += xs[i] * gr[i];
    #pragma unroll
    for (int o = 16; o; o >>= 1) s += __shfl_xor_sync(0xffffffffu, s, o);
    if (lane == 0) lg[w] = s;
    __syncthreads();
    if (threadIdx.x == 0) {
        int i0 = 0;
        #pragma unroll
        for (int e = 1; e < NE; e++) if (lg[e] > lg[i0]) i0 = e;
        int i1 = -1;
        #pragma unroll
        for (int e = 0; e < NE; e++) {
            if (e == i0) continue;
            if (i1 < 0 || lg[e] > lg[i1]) i1 = e;
        }
        float v0 = lg[i0], v1 = lg[i1];
        float ee = expf(v1 - v0);
        float g0 = 1.0f / (1.0f + ee);
        float g1 = ee / (1.0f + ee);
        float mx = v0, se = 0.0f, p[NE];
        #pragma unroll
        for (int e = 0; e < NE; e++) { p[e] = expf(lg[e] - mx); se += p[e]; }
        float inv = 1.0f / se;
        #pragma unroll
        for (int e = 0; e < NE; e++) atomicAdd(&d_probs[e], p[e] * inv);
        atomicAdd(&d_amax[i0], 1);
        int pos0 = atomicAdd(&d_cnt[i0], 1);
        d_tok[i0 * T_TOK + pos0] = t * 2 + 0;
        d_gw [i0 * T_TOK + pos0] = g0;
        int pos1 = atomicAdd(&d_cnt[i1], 1);
        d_tok[i1 * T_TOK + pos1] = t * 2 + 1;
        d_gw [i1 * T_TOK + pos1] = g1;
    }
}

__device__ __forceinline__ float gelu_exact(float v) {
    return 0.5f * v * (1.0f + erff(v * 0.7071067811865475f));
}

// ================= tiled gather-GEMM core =================
// BM=BN=128, BK=16, 256 threads, 8x8 microtile, double-buffered smem.
// A rows gathered via prow (pair ids); B rows contiguous, K-contiguous.

#define BM 128
#define BN 128
#define BK 16

struct TileCtx {
    float As[2][BK][BM];
    float Bs[2][BK][BN];
    int   prow[BM];
};

// GEMM1: H[pair, DFF] = gelu( x[tok] @ w1[e]^T + b1[e] )
__global__ __launch_bounds__(256, 2) void ffn1_kernel(
    const float* __restrict__ x, const float* __restrict__ w1,
    const float* __restrict__ b1)
{
    int e  = blockIdx.z;
    int Me = d_cnt[e];
    int m0 = blockIdx.y * BM;
    if (m0 >= Me) return;
    int n0 = blockIdx.x * BN;

    __shared__ TileCtx S;
    int tid = threadIdx.x;

    if (tid < BM) {
        int m = m0 + tid;
        S.prow[tid] = (m < Me) ? d_tok[e * T_TOK + tid + m0] : -1;
    }
    __syncthreads();

    // loader mapping: 2 threads per row, each 2 float4 (8 floats of K)
    int lrow = tid >> 1;
    int lk   = (tid & 1) * 8;
    int pa = S.prow[lrow];
    const float* aptr = (pa >= 0) ? (x + (size_t)(pa >> 1) * DIM + lk) : nullptr;
    const float* bptr = w1 + (size_t)e * DFF * DIM + (size_t)(n0 + lrow) * DIM + lk;

    int tx = tid & 15, ty = tid >> 4;
    float acc[8][8] = {};
    float4 ra0, ra1, rb0, rb1;

    // prologue: load tile 0
    ra0 = aptr ? *(const float4*)(aptr + 0) : make_float4(0,0,0,0);
    ra1 = aptr ? *(const float4*)(aptr + 4) : make_float4(0,0,0,0);
    rb0 = *(const float4*)(bptr + 0);
    rb1 = *(const float4*)(bptr + 4);
    #pragma unroll
    for (int j = 0; j < 4; j++) {
        S.As[0][lk + j][lrow]     = (&ra0.x)[j];
        S.As[0][lk + 4 + j][lrow] = (&ra1.x)[j];
        S.Bs[0][lk + j][lrow]     = (&rb0.x)[j];
        S.Bs[0][lk + 4 + j][lrow] = (&rb1.x)[j];
    }
    __syncthreads();

    const int NT = DIM / BK;
    for (int kt = 0; kt < NT; kt++) {
        int cur = kt & 1, nxt = cur ^ 1;
        if (kt + 1 < NT) {
            int koff = (kt + 1) * BK;
            ra0 = aptr ? *(const float4*)(aptr + koff)     : make_float4(0,0,0,0);
            ra1 = aptr ? *(const float4*)(aptr + koff + 4) : make_float4(0,0,0,0);
            rb0 = *(const float4*)(bptr + koff);
            rb1 = *(const float4*)(bptr + koff + 4);
        }
        #pragma unroll
        for (int k = 0; k < BK; k++) {
            float4 a0 = *(const float4*)&S.As[cur][k][ty * 8];
            float4 a1 = *(const float4*)&S.As[cur][k][ty * 8 + 4];
            float4 b0 = *(const float4*)&S.Bs[cur][k][tx * 8];
            float4 b1v = *(const float4*)&S.Bs[cur][k][tx * 8 + 4];
            float a[8] = {a0.x,a0.y,a0.z,a0.w,a1.x,a1.y,a1.z,a1.w};
            float b[8] = {b0.x,b0.y,b0.z,b0.w,b1v.x,b1v.y,b1v.z,b1v.w};
            #pragma unroll
            for (int i = 0; i < 8; i++)
                #pragma unroll
                for (int j = 0; j < 8; j++) acc[i][j] += a[i] * b[j];
        }
        if (kt + 1 < NT) {
            #pragma unroll
            for (int j = 0; j < 4; j++) {
                S.As[nxt][lk + j][lrow]     = (&ra0.x)[j];
                S.As[nxt][lk + 4 + j][lrow] = (&ra1.x)[j];
                S.Bs[nxt][lk + j][lrow]     = (&rb0.x)[j];
                S.Bs[nxt][lk + 4 + j][lrow] = (&rb1.x)[j];
            }
        }
        __syncthreads();
    }

    const float* b1e = b1 + e * DFF + n0;
    #pragma unroll
    for (int i = 0; i < 8; i++) {
        int mi = ty * 8 + i;
        int m = m0 + mi;
        if (m >= Me) break;
        int p = S.prow[mi];
        float* dst = d_H + (size_t)p * DFF + n0 + tx * 8;
        float4 o0, o1;
        #pragma unroll
        for (int j = 0; j < 4; j++) {
            (&o0.x)[j] = gelu_exact(acc[i][j]     + b1e[tx * 8 + j]);
            (&o1.x)[j] = gelu_exact(acc[i][4 + j] + b1e[tx * 8 + 4 + j]);
        }
        *(float4*)(dst)     = o0;
        *(float4*)(dst + 4) = o1;
    }
}

// GEMM2: Y[pair, D] = gw * ( H[pair] @ w2[e]^T + b2[e] )
__global__ __launch_bounds__(256, 2) void ffn2_kernel(
    const float* __restrict__ w2, const float* __restrict__ b2)
{
    int e  = blockIdx.z;
    int Me = d_cnt[e];
    int m0 = blockIdx.y * BM;
    if (m0 >= Me) return;
    int n0 = blockIdx.x * BN;

    __shared__ TileCtx S;
    int tid = threadIdx.x;

    if (tid < BM) {
        int m = m0 + tid;
        S.prow[tid] = (m < Me) ? d_tok[e * T_TOK + tid + m0] : -1;
    }
    __syncthreads();

    int lrow = tid >> 1;
    int lk   = (tid & 1) * 8;
    int pa = S.prow[lrow];
    const float* aptr = (pa >= 0) ? (d_H + (size_t)pa * DFF + lk) : nullptr;
    const float* bptr = w2 + (size_t)e * DIM * DFF + (size_t)(n0 + lrow) * DFF + lk;

    int tx = tid & 15, ty = tid >> 4;
    float acc[8][8] = {};
    float4 ra0, ra1, rb0, rb1;

    ra0 = aptr ? *(const float4*)(aptr + 0) : make_float4(0,0,0,0);
    ra1 = aptr ? *(const float4*)(aptr + 4) : make_float4(0,0,0,0);
    rb0 = *(const float4*)(bptr + 0);
    rb1 = *(const float4*)(bptr + 4);
    #pragma unroll
    for (int j = 0; j < 4; j++) {
        S.As[0][lk + j][lrow]     = (&ra0.x)[j];
        S.As[0][lk + 4 + j][lrow] = (&ra1.x)[j];
        S.Bs[0][lk + j][lrow]     = (&rb0.x)[j];
        S.Bs[0][lk + 4 + j][lrow] = (&rb1.x)[j];
    }
    __syncthreads();

    const int NT = DFF / BK;
    for (int kt = 0; kt < NT; kt++) {
        int cur = kt & 1, nxt = cur ^ 1;
        if (kt + 1 < NT) {
            int koff = (kt + 1) * BK;
            ra0 = aptr ? *(const float4*)(aptr + koff)     : make_float4(0,0,0,0);
            ra1 = aptr ? *(const float4*)(aptr + koff + 4) : make_float4(0,0,0,0);
            rb0 = *(const float4*)(bptr + koff);
            rb1 = *(const float4*)(bptr + koff + 4);
        }
        #pragma unroll
        for (int k = 0; k < BK; k++) {
            float4 a0 = *(const float4*)&S.As[cur][k][ty * 8];
            float4 a1 = *(const float4*)&S.As[cur][k][ty * 8 + 4];
            float4 b0 = *(const float4*)&S.Bs[cur][k][tx * 8];
            float4 b1v = *(const float4*)&S.Bs[cur][k][tx * 8 + 4];
            float a[8] = {a0.x,a0.y,a0.z,a0.w,a1.x,a1.y,a1.z,a1.w};
            float b[8] = {b0.x,b0.y,b0.z,b0.w,b1v.x,b1v.y,b1v.z,b1v.w};
            #pragma unroll
            for (int i = 0; i < 8; i++)
                #pragma unroll
                for (int j = 0; j < 8; j++) acc[i][j] += a[i] * b[j];
        }
        if (kt + 1 < NT) {
            #pragma unroll
            for (int j = 0; j < 4; j++) {
                S.As[nxt][lk + j][lrow]     = (&ra0.x)[j];
                S.As[nxt][lk + 4 + j][lrow] = (&ra1.x)[j];
                S.Bs[nxt][lk + j][lrow]     = (&rb0.x)[j];
                S.Bs[nxt][lk + 4 + j][lrow] = (&rb1.x)[j];
            }
        }
        __syncthreads();
    }

    const float* b2e = b2 + e * DIM + n0;
    #pragma unroll
    for (int i = 0; i < 8; i++) {
        int mi = ty * 8 + i;
        int m = m0 + mi;
        if (m >= Me) break;
        int p = S.prow[mi];
        float g = d_gw[e * T_TOK + m];
        float* dst = d_Y + (size_t)p * DIM + n0 + tx * 8;
        float4 o0, o1;
        #pragma unroll
        for (int j = 0; j < 4; j++) {
            (&o0.x)[j] = g * (acc[i][j]     + b2e[tx * 8 + j]);
            (&o1.x)[j] = g * (acc[i][4 + j] + b2e[tx * 8 + 4 + j]);
        }
        *(float4*)(dst)     = o0;
        *(float4*)(dst + 4) = o1;
    }
}

// -------- combine two expert contributions per token --------
__global__ void combine_kernel(float* __restrict__ out)
{
    size_t i = (size_t)blockIdx.x * blockDim.x + threadIdx.x;
    size_t total = (size_t)T_TOK * DIM / 4;
    if (i >= total) return;
    size_t t = i / (DIM / 4);
    size_t d4 = i % (DIM / 4);
    const float4* y0 = (const float4*)(d_Y + (t * 2 + 0) * DIM) + d4;
    const float4* y1 = (const float4*)(d_Y + (t * 2 + 1) * DIM) + d4;
    float4 a = *y0, b = *y1;
    ((float4*)out)[i] = make_float4(a.x + b.x, a.y + b.y, a.z + b.z, a.w + b.w);
}

// -------- load-balance loss --------
__global__ void loss_kernel(float* __restrict__ out, int out_size)
{
    if (threadIdx.x == 0 && blockIdx.x == 0) {
        float lb = 0.0f;
        const float invT = 1.0f / (float)T_TOK;
        #pragma unroll
        for (int e = 0; e < NE; e++)
            lb += ((float)d_amax[e] * invT) * (d_probs[e] * invT);
        lb *= (float)NE;
        if (out_size > T_TOK * DIM) out[T_TOK * DIM] = lb;
    }
}

extern "C" void kernel_launch(void* const* d_in, const int* in_sizes, int n_in,
                              void* d_out, int out_size)
{
    const float* x      = (const float*)d_in[0];
    const float* gate_w = (const float*)d_in[1];
    const float* w1     = (const float*)d_in[2];
    const float* b1     = (const float*)d_in[3];
    const float* w2     = (const float*)d_in[4];
    const float* b2     = (const float*)d_in[5];
    float* out = (float*)d_out;

    zero_kernel<<<1, 32>>>();
    gate_kernel<<<T_TOK, 256>>>(x, gate_w);
    ffn1_kernel<<<dim3(DFF / BN, T_TOK / BM, NE), 256>>>(x, w1, b1);
    ffn2_kernel<<<dim3(DIM / BN, T_TOK / BM, NE), 256>>>(w2, b2);
    {
        size_t total = (size_t)T_TOK * DIM / 4;
        combine_kernel<<<(unsigned)((total + 255) / 256), 256>>>(out);
    }
    loss_kernel<<<1, 32>>>(out, out_size);
}

// round 6
// speedup vs baseline: 3.5158x; 1.7584x over previous
#include <cuda_runtime.h>
#include <cuda_bf16.h>
#include <math.h>
#include <stdint.h>

#define T_TOK 8192
#define DIM   1024
#define DFF   4096
#define NE    8

// -------- scratch (device globals; no allocation) --------
__device__ int   d_cnt[NE];
__device__ int   d_amax[NE];
__device__ float d_probs[NE];
__device__ int   d_tok[NE * T_TOK];   // pair id = t*2+slot
__device__ float d_gw [NE * T_TOK];
__device__ float d_H[(size_t)2 * T_TOK * DFF];
__device__ float d_Y[(size_t)2 * T_TOK * DIM];

// -------- zero counters (graph replays) --------
__global__ void zero_kernel() {
    int i = threadIdx.x;
    if (i < NE) { d_cnt[i] = 0; d_amax[i] = 0; d_probs[i] = 0.0f; }
}

// -------- gating --------
__global__ __launch_bounds__(256) void gate_kernel(
    const float* __restrict__ x, const float* __restrict__ gate_w)
{
    int t = blockIdx.x;
    __shared__ float xs[DIM];
    __shared__ float lg[NE];
    for (int i = threadIdx.x; i < DIM; i += 256) xs[i] = x[(size_t)t * DIM + i];
    __syncthreads();
    int w = threadIdx.x >> 5, lane = threadIdx.x & 31;
    const float* gr = gate_w + w * DIM;
    float s = 0.0f;
    for (int i = lane; i < DIM; i += 32) s += xs[i] * gr[i];
    #pragma unroll
    for (int o = 16; o; o >>= 1) s += __shfl_xor_sync(0xffffffffu, s, o);
    if (lane == 0) lg[w] = s;
    __syncthreads();
    if (threadIdx.x == 0) {
        int i0 = 0;
        #pragma unroll
        for (int e = 1; e < NE; e++) if (lg[e] > lg[i0]) i0 = e;
        int i1 = -1;
        #pragma unroll
        for (int e = 0; e < NE; e++) {
            if (e == i0) continue;
            if (i1 < 0 || lg[e] > lg[i1]) i1 = e;
        }
        float v0 = lg[i0], v1 = lg[i1];
        float ee = expf(v1 - v0);
        float g0 = 1.0f / (1.0f + ee);
        float g1 = ee / (1.0f + ee);
        float mx = v0, se = 0.0f, p[NE];
        #pragma unroll
        for (int e = 0; e < NE; e++) { p[e] = expf(lg[e] - mx); se += p[e]; }
        float inv = 1.0f / se;
        #pragma unroll
        for (int e = 0; e < NE; e++) atomicAdd(&d_probs[e], p[e] * inv);
        atomicAdd(&d_amax[i0], 1);
        int pos0 = atomicAdd(&d_cnt[i0], 1);
        d_tok[i0 * T_TOK + pos0] = t * 2 + 0;
        d_gw [i0 * T_TOK + pos0] = g0;
        int pos1 = atomicAdd(&d_cnt[i1], 1);
        d_tok[i1 * T_TOK + pos1] = t * 2 + 1;
        d_gw [i1 * T_TOK + pos1] = g1;
    }
}

__device__ __forceinline__ float gelu_exact(float v) {
    return 0.5f * v * (1.0f + erff(v * 0.7071067811865475f));
}

// ================= bf16-split (3xMMA) gather-GEMM =================
// BM=BN=128, BK=32, 256 thr (8 warps 2x4), warp tile 64x32, m16n8k16 frags.
// fp32 tiles in smem (stride 36 -> bank-balanced); hi/lo bf16 split at
// fragment load; acc += ah*bh + ah*bl + al*bh (fp32 accumulate).

#define BM 128
#define BN 128
#define BK 32
#define LDS_STRIDE 36

struct SmemT {
    float As[2][BM][LDS_STRIDE];
    float Bs[2][BN][LDS_STRIDE];
    int   prow[BM];
};
#define SMEM_BYTES sizeof(SmemT)

__device__ __forceinline__ uint32_t smem_u32(const void* p) {
    return (uint32_t)__cvta_generic_to_shared(p);
}
__device__ __forceinline__ void cp16(uint32_t dst, const void* src, int src_bytes) {
    asm volatile("cp.async.cg.shared.global [%0], [%1], 16, %2;"
                 :: "r"(dst), "l"(src), "r"(src_bytes) : "memory");
}
__device__ __forceinline__ void cp_commit() {
    asm volatile("cp.async.commit_group;" ::: "memory");
}
template<int N> __device__ __forceinline__ void cp_wait() {
    asm volatile("cp.async.wait_group %0;" :: "n"(N) : "memory");
}
__device__ __forceinline__ void mma16(float* c, const uint32_t* a, const uint32_t* b) {
    asm volatile(
        "mma.sync.aligned.m16n8k16.row.col.f32.bf16.bf16.f32 "
        "{%0,%1,%2,%3}, {%4,%5,%6,%7}, {%8,%9}, {%0,%1,%2,%3};"
        : "+f"(c[0]), "+f"(c[1]), "+f"(c[2]), "+f"(c[3])
        : "r"(a[0]), "r"(a[1]), "r"(a[2]), "r"(a[3]), "r"(b[0]), "r"(b[1]));
}
// split a float2 into packed bf16x2 hi and lo (residual) parts
__device__ __forceinline__ void split2(float2 f, uint32_t& hi, uint32_t& lo) {
    __nv_bfloat162 h = __floats2bfloat162_rn(f.x, f.y);
    float2 hf = __bfloat1622float2(h);
    __nv_bfloat162 l = __floats2bfloat162_rn(f.x - hf.x, f.y - hf.y);
    hi = *reinterpret_cast<uint32_t*>(&h);
    lo = *reinterpret_cast<uint32_t*>(&l);
}

// EPI=0: gelu(acc + bias) -> d_H ; EPI=1: g*(acc + bias) -> d_Y
template<int EPI, int KDIM>
__device__ __forceinline__ void ffn_core(
    const float* __restrict__ Abase, size_t Astride, bool Agather,
    const float* __restrict__ Bbase,           // already offset to (e, n0) row
    const float* __restrict__ bias,            // already offset to (e, n0)
    float* __restrict__ Obase, size_t Ostride, // d_H or d_Y
    int e, int Me, int m0)
{
    extern __shared__ char smem_raw[];
    SmemT* S = (SmemT*)smem_raw;
    int tid = threadIdx.x;

    if (tid < BM) S->prow[tid] = (m0 + tid < Me) ? d_tok[e * T_TOK + m0 + tid] : -1;
    __syncthreads();

    // loader: row = tid>>1 (128 rows), 4 x 16B at cols (tid&1)*16 + q*4
    int lrow = tid >> 1;
    int lc0  = (tid & 1) * 16;
    int pa = S->prow[lrow];
    const float* agp = (pa >= 0)
        ? (Agather ? Abase + (size_t)(pa >> 1) * Astride : Abase + (size_t)pa * Astride)
        : Abase;                                   // dummy, src_bytes=0 zero-fills
    int asz = (pa >= 0) ? 16 : 0;
    const float* bgp = Bbase + (size_t)lrow * KDIM;

    const int NT = KDIM / BK;

    // prologue: tile 0 -> buf 0
    #pragma unroll
    for (int q = 0; q < 4; q++) {
        cp16(smem_u32(&S->As[0][lrow][lc0 + q * 4]), agp + lc0 + q * 4, asz);
        cp16(smem_u32(&S->Bs[0][lrow][lc0 + q * 4]), bgp + lc0 + q * 4, 16);
    }
    cp_commit();

    int wid = tid >> 5, lane = tid & 31;
    int wm = wid >> 2, wn = wid & 3;
    int lr = lane >> 2, lc = lane & 3;
    float acc[4][4][4] = {};

    for (int kt = 0; kt < NT; kt++) {
        int cur = kt & 1;
        if (kt + 1 < NT) {
            int nxt = cur ^ 1;
            int ko = (kt + 1) * BK;
            #pragma unroll
            for (int q = 0; q < 4; q++) {
                cp16(smem_u32(&S->As[nxt][lrow][lc0 + q * 4]), agp + ko + lc0 + q * 4, asz);
                cp16(smem_u32(&S->Bs[nxt][lrow][lc0 + q * 4]), bgp + ko + lc0 + q * 4, 16);
            }
            cp_commit();
            cp_wait<1>();
        } else {
            cp_wait<0>();
        }
        __syncthreads();

        #pragma unroll
        for (int kk = 0; kk < BK; kk += 16) {
            // B fragments: convert once per k-step
            uint32_t bh[4][2], bl[4][2];
            #pragma unroll
            for (int j = 0; j < 4; j++) {
                int n = wn * 32 + j * 8 + lr;
                float2 f0 = *(const float2*)&S->Bs[cur][n][kk + 2 * lc];
                float2 f1 = *(const float2*)&S->Bs[cur][n][kk + 2 * lc + 8];
                split2(f0, bh[j][0], bl[j][0]);
                split2(f1, bh[j][1], bl[j][1]);
            }
            #pragma unroll
            for (int i = 0; i < 4; i++) {
                int r0 = wm * 64 + i * 16 + lr;
                float2 g0 = *(const float2*)&S->As[cur][r0    ][kk + 2 * lc];
                float2 g1 = *(const float2*)&S->As[cur][r0 + 8][kk + 2 * lc];
                float2 g2 = *(const float2*)&S->As[cur][r0    ][kk + 2 * lc + 8];
                float2 g3 = *(const float2*)&S->As[cur][r0 + 8][kk + 2 * lc + 8];
                uint32_t ah[4], al[4];
                split2(g0, ah[0], al[0]);
                split2(g1, ah[1], al[1]);
                split2(g2, ah[2], al[2]);
                split2(g3, ah[3], al[3]);
                #pragma unroll
                for (int j = 0; j < 4; j++) {
                    mma16(acc[i][j], ah, bh[j]);
                    mma16(acc[i][j], ah, bl[j]);
                    mma16(acc[i][j], al, bh[j]);
                }
            }
        }
        __syncthreads();
    }

    // epilogue
    #pragma unroll
    for (int i = 0; i < 4; i++) {
        #pragma unroll
        for (int h = 0; h < 2; h++) {
            int mi = wm * 64 + i * 16 + h * 8 + lr;
            int m  = m0 + mi;
            if (m >= Me) continue;
            int p = S->prow[mi];
            float g = (EPI == 1) ? d_gw[e * T_TOK + m] : 0.0f;
            float* dst = Obase + (size_t)p * Ostride;
            #pragma unroll
            for (int j = 0; j < 4; j++) {
                int col = wn * 32 + j * 8 + 2 * lc;
                float v0 = acc[i][j][h * 2 + 0] + bias[col];
                float v1 = acc[i][j][h * 2 + 1] + bias[col + 1];
                float2 o;
                if (EPI == 0) { o.x = gelu_exact(v0); o.y = gelu_exact(v1); }
                else          { o.x = g * v0;         o.y = g * v1; }
                *(float2*)(dst + col) = o;
            }
        }
    }
}

// GEMM1: H[pair, DFF] = gelu( x[tok] @ w1[e]^T + b1[e] )
__global__ __launch_bounds__(256, 2) void ffn1_kernel(
    const float* __restrict__ x, const float* __restrict__ w1,
    const float* __restrict__ b1)
{
    int e  = blockIdx.z;
    int Me = d_cnt[e];
    int m0 = blockIdx.y * BM;
    if (m0 >= Me) return;
    int n0 = blockIdx.x * BN;
    ffn_core<0, DIM>(x, DIM, true,
                     w1 + ((size_t)e * DFF + n0) * DIM,
                     b1 + (size_t)e * DFF + n0,
                     d_H + n0, DFF, e, Me, m0);
}

// GEMM2: Y[pair, D] = gw * ( H[pair] @ w2[e]^T + b2[e] )
__global__ __launch_bounds__(256, 2) void ffn2_kernel(
    const float* __restrict__ w2, const float* __restrict__ b2)
{
    int e  = blockIdx.z;
    int Me = d_cnt[e];
    int m0 = blockIdx.y * BM;
    if (m0 >= Me) return;
    int n0 = blockIdx.x * BN;
    ffn_core<1, DFF>(d_H, DFF, false,
                     w2 + ((size_t)e * DIM + n0) * DFF,
                     b2 + (size_t)e * DIM + n0,
                     d_Y + n0, DIM, e, Me, m0);
}

// -------- combine two expert contributions per token --------
__global__ void combine_kernel(float* __restrict__ out)
{
    size_t i = (size_t)blockIdx.x * blockDim.x + threadIdx.x;
    size_t total = (size_t)T_TOK * DIM / 4;
    if (i >= total) return;
    size_t t = i / (DIM / 4);
    size_t d4 = i % (DIM / 4);
    const float4* y0 = (const float4*)(d_Y + (t * 2 + 0) * DIM) + d4;
    const float4* y1 = (const float4*)(d_Y + (t * 2 + 1) * DIM) + d4;
    float4 a = *y0, b = *y1;
    ((float4*)out)[i] = make_float4(a.x + b.x, a.y + b.y, a.z + b.z, a.w + b.w);
}

// -------- load-balance loss --------
__global__ void loss_kernel(float* __restrict__ out, int out_size)
{
    if (threadIdx.x == 0 && blockIdx.x == 0) {
        float lb = 0.0f;
        const float invT = 1.0f / (float)T_TOK;
        #pragma unroll
        for (int e = 0; e < NE; e++)
            lb += ((float)d_amax[e] * invT) * (d_probs[e] * invT);
        lb *= (float)NE;
        if (out_size > T_TOK * DIM) out[T_TOK * DIM] = lb;
    }
}

extern "C" void kernel_launch(void* const* d_in, const int* in_sizes, int n_in,
                              void* d_out, int out_size)
{
    const float* x      = (const float*)d_in[0];
    const float* gate_w = (const float*)d_in[1];
    const float* w1     = (const float*)d_in[2];
    const float* b1     = (const float*)d_in[3];
    const float* w2     = (const float*)d_in[4];
    const float* b2     = (const float*)d_in[5];
    float* out = (float*)d_out;

    cudaFuncSetAttribute(ffn1_kernel, cudaFuncAttributeMaxDynamicSharedMemorySize, SMEM_BYTES);
    cudaFuncSetAttribute(ffn2_kernel, cudaFuncAttributeMaxDynamicSharedMemorySize, SMEM_BYTES);

    zero_kernel<<<1, 32>>>();
    gate_kernel<<<T_TOK, 256>>>(x, gate_w);
    ffn1_kernel<<<dim3(DFF / BN, T_TOK / BM, NE), 256, SMEM_BYTES>>>(x, w1, b1);
    ffn2_kernel<<<dim3(DIM / BN, T_TOK / BM, NE), 256, SMEM_BYTES>>>(w2, b2);
    {
        size_t total = (size_t)T_TOK * DIM / 4;
        combine_kernel<<<(unsigned)((total + 255) / 256), 256>>>(out);
    }
    loss_kernel<<<1, 32>>>(out, out_size);
}

// round 7
// speedup vs baseline: 4.3085x; 1.2255x over previous
#include <cuda_runtime.h>
#include <cuda_bf16.h>
#include <math.h>
#include <stdint.h>

#define T_TOK 8192
#define DIM   1024
#define DFF   4096
#define NE    8

// -------- scratch (device globals; no allocation) --------
__device__ int   d_cnt[NE];
__device__ int   d_amax[NE];
__device__ float d_probs[NE];
__device__ int   d_tok[NE * T_TOK];   // pair id = t*2+slot
__device__ float d_gw [NE * T_TOK];
__device__ float d_Y[(size_t)2 * T_TOK * DIM];
// pre-split bf16 hi/lo operands
__device__ __nv_bfloat16 d_xh[(size_t)T_TOK * DIM];
__device__ __nv_bfloat16 d_xl[(size_t)T_TOK * DIM];
__device__ __nv_bfloat16 d_w1h[(size_t)NE * DFF * DIM];
__device__ __nv_bfloat16 d_w1l[(size_t)NE * DFF * DIM];
__device__ __nv_bfloat16 d_w2h[(size_t)NE * DIM * DFF];
__device__ __nv_bfloat16 d_w2l[(size_t)NE * DIM * DFF];
__device__ __nv_bfloat16 d_Hh[(size_t)2 * T_TOK * DFF];
__device__ __nv_bfloat16 d_Hl[(size_t)2 * T_TOK * DFF];

// -------- zero counters (graph replays) --------
__global__ void zero_kernel() {
    int i = threadIdx.x;
    if (i < NE) { d_cnt[i] = 0; d_amax[i] = 0; d_probs[i] = 0.0f; }
}

// -------- fp32 -> bf16 hi/lo split (grid-stride, float4) --------
__global__ __launch_bounds__(256) void split_kernel(
    const float* __restrict__ src, __nv_bfloat16* __restrict__ hi,
    __nv_bfloat16* __restrict__ lo, size_t n4)
{
    for (size_t i = (size_t)blockIdx.x * blockDim.x + threadIdx.x; i < n4;
         i += (size_t)gridDim.x * blockDim.x) {
        float4 v = ((const float4*)src)[i];
        __nv_bfloat162 h0 = __floats2bfloat162_rn(v.x, v.y);
        __nv_bfloat162 h1 = __floats2bfloat162_rn(v.z, v.w);
        float2 f0 = __bfloat1622float2(h0);
        float2 f1 = __bfloat1622float2(h1);
        __nv_bfloat162 l0 = __floats2bfloat162_rn(v.x - f0.x, v.y - f0.y);
        __nv_bfloat162 l1 = __floats2bfloat162_rn(v.z - f1.x, v.w - f1.y);
        ((__nv_bfloat162*)hi)[2 * i]     = h0;
        ((__nv_bfloat162*)hi)[2 * i + 1] = h1;
        ((__nv_bfloat162*)lo)[2 * i]     = l0;
        ((__nv_bfloat162*)lo)[2 * i + 1] = l1;
    }
}

// -------- gating --------
__global__ __launch_bounds__(256) void gate_kernel(
    const float* __restrict__ x, const float* __restrict__ gate_w)
{
    int t = blockIdx.x;
    __shared__ float xs[DIM];
    __shared__ float lg[NE];
    for (int i = threadIdx.x; i < DIM; i += 256) xs[i] = x[(size_t)t * DIM + i];
    __syncthreads();
    int w = threadIdx.x >> 5, lane = threadIdx.x & 31;
    const float* gr = gate_w + w * DIM;
    float s = 0.0f;
    for (int i = lane; i < DIM; i += 32) s += xs[i] * gr[i];
    #pragma unroll
    for (int o = 16; o; o >>= 1) s += __shfl_xor_sync(0xffffffffu, s, o);
    if (lane == 0) lg[w] = s;
    __syncthreads();
    if (threadIdx.x == 0) {
        int i0 = 0;
        #pragma unroll
        for (int e = 1; e < NE; e++) if (lg[e] > lg[i0]) i0 = e;
        int i1 = -1;
        #pragma unroll
        for (int e = 0; e < NE; e++) {
            if (e == i0) continue;
            if (i1 < 0 || lg[e] > lg[i1]) i1 = e;
        }
        float v0 = lg[i0], v1 = lg[i1];
        float ee = expf(v1 - v0);
        float g0 = 1.0f / (1.0f + ee);
        float g1 = ee / (1.0f + ee);
        float mx = v0, se = 0.0f, p[NE];
        #pragma unroll
        for (int e = 0; e < NE; e++) { p[e] = expf(lg[e] - mx); se += p[e]; }
        float inv = 1.0f / se;
        #pragma unroll
        for (int e = 0; e < NE; e++) atomicAdd(&d_probs[e], p[e] * inv);
        atomicAdd(&d_amax[i0], 1);
        int pos0 = atomicAdd(&d_cnt[i0], 1);
        d_tok[i0 * T_TOK + pos0] = t * 2 + 0;
        d_gw [i0 * T_TOK + pos0] = g0;
        int pos1 = atomicAdd(&d_cnt[i1], 1);
        d_tok[i1 * T_TOK + pos1] = t * 2 + 1;
        d_gw [i1 * T_TOK + pos1] = g1;
    }
}

__device__ __forceinline__ float gelu_exact(float v) {
    return 0.5f * v * (1.0f + erff(v * 0.7071067811865475f));
}

// ================= bf16 hi/lo (3xMMA) gather-GEMM, pre-split operands =====
// BM=BN=128, BK=32, 256 thr (8 warps 2x4), warp tile 64x32, m16n8k16.
// smem row stride 40 bf16 (80B): fragment loads hit 32 distinct banks.

#define BM 128
#define BN 128
#define BK 32
#define SST 40   // smem row stride in bf16

struct SmemT {
    __nv_bfloat16 Ah[2][BM][SST];
    __nv_bfloat16 Al[2][BM][SST];
    __nv_bfloat16 Bh[2][BN][SST];
    __nv_bfloat16 Bl[2][BN][SST];
    int prow[BM];
};
#define SMEM_BYTES sizeof(SmemT)

__device__ __forceinline__ uint32_t smem_u32(const void* p) {
    return (uint32_t)__cvta_generic_to_shared(p);
}
__device__ __forceinline__ void cp16(uint32_t dst, const void* src, int src_bytes) {
    asm volatile("cp.async.cg.shared.global [%0], [%1], 16, %2;"
                 :: "r"(dst), "l"(src), "r"(src_bytes) : "memory");
}
__device__ __forceinline__ void cp_commit() {
    asm volatile("cp.async.commit_group;" ::: "memory");
}
template<int N> __device__ __forceinline__ void cp_wait() {
    asm volatile("cp.async.wait_group %0;" :: "n"(N) : "memory");
}
__device__ __forceinline__ void mma16(float* c, const uint32_t* a, const uint32_t* b) {
    asm volatile(
        "mma.sync.aligned.m16n8k16.row.col.f32.bf16.bf16.f32 "
        "{%0,%1,%2,%3}, {%4,%5,%6,%7}, {%8,%9}, {%0,%1,%2,%3};"
        : "+f"(c[0]), "+f"(c[1]), "+f"(c[2]), "+f"(c[3])
        : "r"(a[0]), "r"(a[1]), "r"(a[2]), "r"(a[3]), "r"(b[0]), "r"(b[1]));
}
#define U32AT(arr, r, c) (*(const uint32_t*)&(arr)[r][c])

// EPI=0: gelu(acc+bias) -> Hh/Hl ; EPI=1: g*(acc+bias) -> d_Y
template<int EPI, int KDIM>
__device__ __forceinline__ void ffn_core(
    const __nv_bfloat16* __restrict__ Ah, const __nv_bfloat16* __restrict__ Al,
    size_t Astride, bool Agather,
    const __nv_bfloat16* __restrict__ Bh, const __nv_bfloat16* __restrict__ Bl,
    const float* __restrict__ bias,       // offset to (e, n0)
    int e, int Me, int m0, int n0)
{
    extern __shared__ char smem_raw[];
    SmemT* S = (SmemT*)smem_raw;
    int tid = threadIdx.x;

    if (tid < BM) S->prow[tid] = (m0 + tid < Me) ? d_tok[e * T_TOK + m0 + tid] : -1;
    __syncthreads();

    // loader: row = tid>>1, two 16B chunks (8 bf16 each) at (tid&1)*16
    int lrow = tid >> 1;
    int lcb  = (tid & 1) * 16;           // bf16 col of first chunk
    int pa = S->prow[lrow];
    size_t arow = (pa >= 0) ? (Agather ? (size_t)(pa >> 1) : (size_t)pa) * Astride : 0;
    int asz = (pa >= 0) ? 16 : 0;
    const __nv_bfloat16* agh = Ah + arow + lcb;
    const __nv_bfloat16* agl = Al + arow + lcb;
    const __nv_bfloat16* bgh = Bh + (size_t)lrow * KDIM + lcb;
    const __nv_bfloat16* bgl = Bl + (size_t)lrow * KDIM + lcb;

    const int NT = KDIM / BK;

    #pragma unroll
    for (int q = 0; q < 2; q++) {   // chunk q covers bf16 cols lcb + q*8
        cp16(smem_u32(&S->Ah[0][lrow][lcb + q * 8]), agh + q * 8, asz);
        cp16(smem_u32(&S->Al[0][lrow][lcb + q * 8]), agl + q * 8, asz);
        cp16(smem_u32(&S->Bh[0][lrow][lcb + q * 8]), bgh + q * 8, 16);
        cp16(smem_u32(&S->Bl[0][lrow][lcb + q * 8]), bgl + q * 8, 16);
    }
    cp_commit();

    int wid = tid >> 5, lane = tid & 31;
    int wm = wid >> 2, wn = wid & 3;
    int lr = lane >> 2, lc = lane & 3;
    float acc[4][4][4] = {};

    for (int kt = 0; kt < NT; kt++) {
        int cur = kt & 1;
        if (kt + 1 < NT) {
            int nxt = cur ^ 1;
            int ko = (kt + 1) * BK;
            #pragma unroll
            for (int q = 0; q < 2; q++) {
                cp16(smem_u32(&S->Ah[nxt][lrow][lcb + q * 8]), agh + ko + q * 8, asz);
                cp16(smem_u32(&S->Al[nxt][lrow][lcb + q * 8]), agl + ko + q * 8, asz);
                cp16(smem_u32(&S->Bh[nxt][lrow][lcb + q * 8]), bgh + ko + q * 8, 16);
                cp16(smem_u32(&S->Bl[nxt][lrow][lcb + q * 8]), bgl + ko + q * 8, 16);
            }
            cp_commit();
            cp_wait<1>();
        } else {
            cp_wait<0>();
        }
        __syncthreads();

        #pragma unroll
        for (int kk = 0; kk < BK; kk += 16) {
            uint32_t bh[4][2], bl[4][2];
            #pragma unroll
            for (int j = 0; j < 4; j++) {
                int n = wn * 32 + j * 8 + lr;
                bh[j][0] = U32AT(S->Bh[cur], n, kk + 2 * lc);
                bh[j][1] = U32AT(S->Bh[cur], n, kk + 2 * lc + 8);
                bl[j][0] = U32AT(S->Bl[cur], n, kk + 2 * lc);
                bl[j][1] = U32AT(S->Bl[cur], n, kk + 2 * lc + 8);
            }
            #pragma unroll
            for (int i = 0; i < 4; i++) {
                int r0 = wm * 64 + i * 16 + lr;
                uint32_t ah[4], al[4];
                ah[0] = U32AT(S->Ah[cur], r0,     kk + 2 * lc);
                ah[1] = U32AT(S->Ah[cur], r0 + 8, kk + 2 * lc);
                ah[2] = U32AT(S->Ah[cur], r0,     kk + 2 * lc + 8);
                ah[3] = U32AT(S->Ah[cur], r0 + 8, kk + 2 * lc + 8);
                al[0] = U32AT(S->Al[cur], r0,     kk + 2 * lc);
                al[1] = U32AT(S->Al[cur], r0 + 8, kk + 2 * lc);
                al[2] = U32AT(S->Al[cur], r0,     kk + 2 * lc + 8);
                al[3] = U32AT(S->Al[cur], r0 + 8, kk + 2 * lc + 8);
                #pragma unroll
                for (int j = 0; j < 4; j++) {
                    mma16(acc[i][j], ah, bh[j]);
                    mma16(acc[i][j], ah, bl[j]);
                    mma16(acc[i][j], al, bh[j]);
                }
            }
        }
        __syncthreads();
    }

    // epilogue
    #pragma unroll
    for (int i = 0; i < 4; i++) {
        #pragma unroll
        for (int h = 0; h < 2; h++) {
            int mi = wm * 64 + i * 16 + h * 8 + lr;
            int m  = m0 + mi;
            if (m >= Me) continue;
            int p = S->prow[mi];
            float g = (EPI == 1) ? d_gw[e * T_TOK + m] : 0.0f;
            #pragma unroll
            for (int j = 0; j < 4; j++) {
                int col = wn * 32 + j * 8 + 2 * lc;
                float v0 = acc[i][j][h * 2 + 0] + bias[col];
                float v1 = acc[i][j][h * 2 + 1] + bias[col + 1];
                if (EPI == 0) {
                    v0 = gelu_exact(v0); v1 = gelu_exact(v1);
                    size_t off = (size_t)p * DFF + n0 + col;
                    __nv_bfloat162 hh = __floats2bfloat162_rn(v0, v1);
                    float2 hf = __bfloat1622float2(hh);
                    __nv_bfloat162 ll = __floats2bfloat162_rn(v0 - hf.x, v1 - hf.y);
                    *(__nv_bfloat162*)(d_Hh + off) = hh;
                    *(__nv_bfloat162*)(d_Hl + off) = ll;
                } else {
                    float2 o = make_float2(g * v0, g * v1);
                    *(float2*)(d_Y + (size_t)p * DIM + n0 + col) = o;
                }
            }
        }
    }
}

// GEMM1: H[pair, DFF] = gelu( x[tok] @ w1[e]^T + b1[e] )
__global__ __launch_bounds__(256, 2) void ffn1_kernel(const float* __restrict__ b1)
{
    int e  = blockIdx.z;
    int Me = d_cnt[e];
    int m0 = blockIdx.y * BM;
    if (m0 >= Me) return;
    int n0 = blockIdx.x * BN;
    ffn_core<0, DIM>(d_xh, d_xl, DIM, true,
                     d_w1h + ((size_t)e * DFF + n0) * DIM,
                     d_w1l + ((size_t)e * DFF + n0) * DIM,
                     b1 + (size_t)e * DFF + n0,
                     e, Me, m0, n0);
}

// GEMM2: Y[pair, D] = gw * ( H[pair] @ w2[e]^T + b2[e] )
__global__ __launch_bounds__(256, 2) void ffn2_kernel(const float* __restrict__ b2)
{
    int e  = blockIdx.z;
    int Me = d_cnt[e];
    int m0 = blockIdx.y * BM;
    if (m0 >= Me) return;
    int n0 = blockIdx.x * BN;
    ffn_core<1, DFF>(d_Hh, d_Hl, DFF, false,
                     d_w2h + ((size_t)e * DIM + n0) * DFF,
                     d_w2l + ((size_t)e * DIM + n0) * DFF,
                     b2 + (size_t)e * DIM + n0,
                     e, Me, m0, n0);
}

// -------- combine two expert contributions per token --------
__global__ void combine_kernel(float* __restrict__ out)
{
    size_t i = (size_t)blockIdx.x * blockDim.x + threadIdx.x;
    size_t total = (size_t)T_TOK * DIM / 4;
    if (i >= total) return;
    size_t t = i / (DIM / 4);
    size_t d4 = i % (DIM / 4);
    const float4* y0 = (const float4*)(d_Y + (t * 2 + 0) * DIM) + d4;
    const float4* y1 = (const float4*)(d_Y + (t * 2 + 1) * DIM) + d4;
    float4 a = *y0, b = *y1;
    ((float4*)out)[i] = make_float4(a.x + b.x, a.y + b.y, a.z + b.z, a.w + b.w);
}

// -------- load-balance loss --------
__global__ void loss_kernel(float* __restrict__ out, int out_size)
{
    if (threadIdx.x == 0 && blockIdx.x == 0) {
        float lb = 0.0f;
        const float invT = 1.0f / (float)T_TOK;
        #pragma unroll
        for (int e = 0; e < NE; e++)
            lb += ((float)d_amax[e] * invT) * (d_probs[e] * invT);
        lb *= (float)NE;
        if (out_size > T_TOK * DIM) out[T_TOK * DIM] = lb;
    }
}

extern "C" void kernel_launch(void* const* d_in, const int* in_sizes, int n_in,
                              void* d_out, int out_size)
{
    const float* x      = (const float*)d_in[0];
    const float* gate_w = (const float*)d_in[1];
    const float* w1     = (const float*)d_in[2];
    const float* b1     = (const float*)d_in[3];
    const float* w2     = (const float*)d_in[4];
    const float* b2     = (const float*)d_in[5];
    float* out = (float*)d_out;

    cudaFuncSetAttribute(ffn1_kernel, cudaFuncAttributeMaxDynamicSharedMemorySize, SMEM_BYTES);
    cudaFuncSetAttribute(ffn2_kernel, cudaFuncAttributeMaxDynamicSharedMemorySize, SMEM_BYTES);

    zero_kernel<<<1, 32>>>();
    gate_kernel<<<T_TOK, 256>>>(x, gate_w);

    __nv_bfloat16 *xh, *xl, *w1h, *w1l, *w2h, *w2l;
    cudaGetSymbolAddress((void**)&xh,  d_xh);
    cudaGetSymbolAddress((void**)&xl,  d_xl);
    cudaGetSymbolAddress((void**)&w1h, d_w1h);
    cudaGetSymbolAddress((void**)&w1l, d_w1l);
    cudaGetSymbolAddress((void**)&w2h, d_w2h);
    cudaGetSymbolAddress((void**)&w2l, d_w2l);

    split_kernel<<<2048, 256>>>(x,  xh,  xl,  (size_t)T_TOK * DIM / 4);
    split_kernel<<<8192, 256>>>(w1, w1h, w1l, (size_t)NE * DFF * DIM / 4);
    split_kernel<<<8192, 256>>>(w2, w2h, w2l, (size_t)NE * DIM * DFF / 4);

    ffn1_kernel<<<dim3(DFF / BN, T_TOK / BM, NE), 256, SMEM_BYTES>>>(b1);
    ffn2_kernel<<<dim3(DIM / BN, T_TOK / BM, NE), 256, SMEM_BYTES>>>(b2);
    {
        size_t total = (size_t)T_TOK * DIM / 4;
        combine_kernel<<<(unsigned)((total + 255) / 256), 256>>>(out);
    }
    loss_kernel<<<1, 32>>>(out, out_size);
}

// round 8
// speedup vs baseline: 4.6288x; 1.0744x over previous
#include <cuda_runtime.h>
#include <cuda_bf16.h>
#include <math.h>
#include <stdint.h>

#define T_TOK 8192
#define DIM   1024
#define DFF   4096
#define NE    8

// -------- scratch (device globals; no allocation) --------
__device__ int   d_cnt[NE];
__device__ int   d_amax[NE];
__device__ float d_probs[NE];
__device__ int   d_tok[NE * T_TOK];   // pair id = t*2+slot
__device__ float d_gw [NE * T_TOK];
__device__ float d_Y[(size_t)2 * T_TOK * DIM];
// pre-split bf16 hi/lo operands
__device__ __nv_bfloat16 d_xh[(size_t)T_TOK * DIM];
__device__ __nv_bfloat16 d_xl[(size_t)T_TOK * DIM];
__device__ __nv_bfloat16 d_w1h[(size_t)NE * DFF * DIM];
__device__ __nv_bfloat16 d_w1l[(size_t)NE * DFF * DIM];
__device__ __nv_bfloat16 d_w2h[(size_t)NE * DIM * DFF];
__device__ __nv_bfloat16 d_w2l[(size_t)NE * DIM * DFF];
__device__ __nv_bfloat16 d_Hh[(size_t)2 * T_TOK * DFF];
__device__ __nv_bfloat16 d_Hl[(size_t)2 * T_TOK * DFF];

// -------- zero counters (graph replays) --------
__global__ void zero_kernel() {
    int i = threadIdx.x;
    if (i < NE) { d_cnt[i] = 0; d_amax[i] = 0; d_probs[i] = 0.0f; }
}

// -------- fp32 -> bf16 hi/lo split (grid-stride, float4) --------
__global__ __launch_bounds__(256) void split_kernel(
    const float* __restrict__ src, __nv_bfloat16* __restrict__ hi,
    __nv_bfloat16* __restrict__ lo, size_t n4)
{
    for (size_t i = (size_t)blockIdx.x * blockDim.x + threadIdx.x; i < n4;
         i += (size_t)gridDim.x * blockDim.x) {
        float4 v = ((const float4*)src)[i];
        __nv_bfloat162 h0 = __floats2bfloat162_rn(v.x, v.y);
        __nv_bfloat162 h1 = __floats2bfloat162_rn(v.z, v.w);
        float2 f0 = __bfloat1622float2(h0);
        float2 f1 = __bfloat1622float2(h1);
        __nv_bfloat162 l0 = __floats2bfloat162_rn(v.x - f0.x, v.y - f0.y);
        __nv_bfloat162 l1 = __floats2bfloat162_rn(v.z - f1.x, v.w - f1.y);
        ((__nv_bfloat162*)hi)[2 * i]     = h0;
        ((__nv_bfloat162*)hi)[2 * i + 1] = h1;
        ((__nv_bfloat162*)lo)[2 * i]     = l0;
        ((__nv_bfloat162*)lo)[2 * i + 1] = l1;
    }
}

// -------- gating --------
__global__ __launch_bounds__(256) void gate_kernel(
    const float* __restrict__ x, const float* __restrict__ gate_w)
{
    int t = blockIdx.x;
    __shared__ float xs[DIM];
    __shared__ float lg[NE];
    for (int i = threadIdx.x; i < DIM; i += 256) xs[i] = x[(size_t)t * DIM + i];
    __syncthreads();
    int w = threadIdx.x >> 5, lane = threadIdx.x & 31;
    const float* gr = gate_w + w * DIM;
    float s = 0.0f;
    for (int i = lane; i < DIM; i += 32) s += xs[i] * gr[i];
    #pragma unroll
    for (int o = 16; o; o >>= 1) s += __shfl_xor_sync(0xffffffffu, s, o);
    if (lane == 0) lg[w] = s;
    __syncthreads();
    if (threadIdx.x == 0) {
        int i0 = 0;
        #pragma unroll
        for (int e = 1; e < NE; e++) if (lg[e] > lg[i0]) i0 = e;
        int i1 = -1;
        #pragma unroll
        for (int e = 0; e < NE; e++) {
            if (e == i0) continue;
            if (i1 < 0 || lg[e] > lg[i1]) i1 = e;
        }
        float v0 = lg[i0], v1 = lg[i1];
        float ee = expf(v1 - v0);
        float g0 = 1.0f / (1.0f + ee);
        float g1 = ee / (1.0f + ee);
        float mx = v0, se = 0.0f, p[NE];
        #pragma unroll
        for (int e = 0; e < NE; e++) { p[e] = expf(lg[e] - mx); se += p[e]; }
        float inv = 1.0f / se;
        #pragma unroll
        for (int e = 0; e < NE; e++) atomicAdd(&d_probs[e], p[e] * inv);
        atomicAdd(&d_amax[i0], 1);
        int pos0 = atomicAdd(&d_cnt[i0], 1);
        d_tok[i0 * T_TOK + pos0] = t * 2 + 0;
        d_gw [i0 * T_TOK + pos0] = g0;
        int pos1 = atomicAdd(&d_cnt[i1], 1);
        d_tok[i1 * T_TOK + pos1] = t * 2 + 1;
        d_gw [i1 * T_TOK + pos1] = g1;
    }
}

__device__ __forceinline__ float gelu_exact(float v) {
    return 0.5f * v * (1.0f + erff(v * 0.7071067811865475f));
}

// ================= bf16 hi/lo (3xMMA) gather-GEMM, ldmatrix fragments =====
// BM=BN=128, BK=32, 256 thr (8 warps 2x4), warp tile 64x32, m16n8k16.
// smem row stride 40 bf16 (80B): LDSM phases hit all 32 banks, conflict-free.

#define BM 128
#define BN 128
#define BK 32
#define SST 40                      // smem row stride in bf16
#define ROWB (SST * 2)              // 80 bytes per row

struct SmemT {
    __nv_bfloat16 Ah[2][BM][SST];
    __nv_bfloat16 Al[2][BM][SST];
    __nv_bfloat16 Bh[2][BN][SST];
    __nv_bfloat16 Bl[2][BN][SST];
    int prow[BM];
};
#define SMEM_BYTES sizeof(SmemT)

__device__ __forceinline__ uint32_t smem_u32(const void* p) {
    return (uint32_t)__cvta_generic_to_shared(p);
}
__device__ __forceinline__ void cp16(uint32_t dst, const void* src, int src_bytes) {
    asm volatile("cp.async.cg.shared.global [%0], [%1], 16, %2;"
                 :: "r"(dst), "l"(src), "r"(src_bytes) : "memory");
}
__device__ __forceinline__ void cp_commit() {
    asm volatile("cp.async.commit_group;" ::: "memory");
}
template<int N> __device__ __forceinline__ void cp_wait() {
    asm volatile("cp.async.wait_group %0;" :: "n"(N) : "memory");
}
__device__ __forceinline__ void mma16(float* c, const uint32_t* a, const uint32_t* b) {
    asm volatile(
        "mma.sync.aligned.m16n8k16.row.col.f32.bf16.bf16.f32 "
        "{%0,%1,%2,%3}, {%4,%5,%6,%7}, {%8,%9}, {%0,%1,%2,%3};"
        : "+f"(c[0]), "+f"(c[1]), "+f"(c[2]), "+f"(c[3])
        : "r"(a[0]), "r"(a[1]), "r"(a[2]), "r"(a[3]), "r"(b[0]), "r"(b[1]));
}
__device__ __forceinline__ void ldsm4(uint32_t* r, uint32_t addr) {
    asm volatile("ldmatrix.sync.aligned.m8n8.x4.shared.b16 {%0,%1,%2,%3}, [%4];"
                 : "=r"(r[0]), "=r"(r[1]), "=r"(r[2]), "=r"(r[3]) : "r"(addr));
}

// EPI=0: gelu(acc+bias) -> Hh/Hl ; EPI=1: g*(acc+bias) -> d_Y
template<int EPI, int KDIM>
__device__ __forceinline__ void ffn_core(
    const __nv_bfloat16* __restrict__ Ah, const __nv_bfloat16* __restrict__ Al,
    size_t Astride, bool Agather,
    const __nv_bfloat16* __restrict__ Bh, const __nv_bfloat16* __restrict__ Bl,
    const float* __restrict__ bias,       // offset to (e, n0)
    int e, int Me, int m0, int n0)
{
    extern __shared__ char smem_raw[];
    SmemT* S = (SmemT*)smem_raw;
    int tid = threadIdx.x;

    if (tid < BM) S->prow[tid] = (m0 + tid < Me) ? d_tok[e * T_TOK + m0 + tid] : -1;
    __syncthreads();

    // loader: row = tid>>1, two 16B chunks (8 bf16 each) at (tid&1)*16
    int lrow = tid >> 1;
    int lcb  = (tid & 1) * 16;
    int pa = S->prow[lrow];
    size_t arow = (pa >= 0) ? (Agather ? (size_t)(pa >> 1) : (size_t)pa) * Astride : 0;
    int asz = (pa >= 0) ? 16 : 0;
    const __nv_bfloat16* agh = Ah + arow + lcb;
    const __nv_bfloat16* agl = Al + arow + lcb;
    const __nv_bfloat16* bgh = Bh + (size_t)lrow * KDIM + lcb;
    const __nv_bfloat16* bgl = Bl + (size_t)lrow * KDIM + lcb;

    const int NT = KDIM / BK;

    #pragma unroll
    for (int q = 0; q < 2; q++) {
        cp16(smem_u32(&S->Ah[0][lrow][lcb + q * 8]), agh + q * 8, asz);
        cp16(smem_u32(&S->Al[0][lrow][lcb + q * 8]), agl + q * 8, asz);
        cp16(smem_u32(&S->Bh[0][lrow][lcb + q * 8]), bgh + q * 8, 16);
        cp16(smem_u32(&S->Bl[0][lrow][lcb + q * 8]), bgl + q * 8, 16);
    }
    cp_commit();

    int wid = tid >> 5, lane = tid & 31;
    int wm = wid >> 2, wn = wid & 3;
    int lr = lane >> 2, lc = lane & 3;

    // ldmatrix lane->address mapping
    int aRow = wm * 64 + (lane & 7) + ((lane >> 3) & 1) * 8;
    int aK   = (lane >> 4) * 8;
    int bMat = lane >> 3;
    int bRow = wn * 32 + (bMat >> 1) * 8 + (lane & 7);
    int bK   = (bMat & 1) * 8;
    uint32_t aBH[2], aBL[2], bBH[2], bBL[2];
    #pragma unroll
    for (int b = 0; b < 2; b++) {
        aBH[b] = smem_u32(&S->Ah[b][aRow][aK]);
        aBL[b] = smem_u32(&S->Al[b][aRow][aK]);
        bBH[b] = smem_u32(&S->Bh[b][bRow][bK]);
        bBL[b] = smem_u32(&S->Bl[b][bRow][bK]);
    }

    float acc[4][4][4] = {};

    for (int kt = 0; kt < NT; kt++) {
        int cur = kt & 1;
        if (kt + 1 < NT) {
            int nxt = cur ^ 1;
            int ko = (kt + 1) * BK;
            #pragma unroll
            for (int q = 0; q < 2; q++) {
                cp16(smem_u32(&S->Ah[nxt][lrow][lcb + q * 8]), agh + ko + q * 8, asz);
                cp16(smem_u32(&S->Al[nxt][lrow][lcb + q * 8]), agl + ko + q * 8, asz);
                cp16(smem_u32(&S->Bh[nxt][lrow][lcb + q * 8]), bgh + ko + q * 8, 16);
                cp16(smem_u32(&S->Bl[nxt][lrow][lcb + q * 8]), bgl + ko + q * 8, 16);
            }
            cp_commit();
            cp_wait<1>();
        } else {
            cp_wait<0>();
        }
        __syncthreads();

        #pragma unroll
        for (int kk = 0; kk < BK; kk += 16) {
            // B fragments for all 4 j: two x4 loads per hi/lo
            uint32_t bh[2][4], bl[2][4];
            ldsm4(bh[0], bBH[cur] + kk * 2);
            ldsm4(bh[1], bBH[cur] + 16 * ROWB + kk * 2);
            ldsm4(bl[0], bBL[cur] + kk * 2);
            ldsm4(bl[1], bBL[cur] + 16 * ROWB + kk * 2);
            #pragma unroll
            for (int i = 0; i < 4; i++) {
                uint32_t ah[4], al[4];
                ldsm4(ah, aBH[cur] + i * 16 * ROWB + kk * 2);
                ldsm4(al, aBL[cur] + i * 16 * ROWB + kk * 2);
                #pragma unroll
                for (int j = 0; j < 4; j++) {
                    const uint32_t* bhp = &bh[j >> 1][(j & 1) * 2];
                    const uint32_t* blp = &bl[j >> 1][(j & 1) * 2];
                    mma16(acc[i][j], ah, bhp);
                    mma16(acc[i][j], ah, blp);
                    mma16(acc[i][j], al, bhp);
                }
            }
        }
        __syncthreads();
    }

    // epilogue
    #pragma unroll
    for (int i = 0; i < 4; i++) {
        #pragma unroll
        for (int h = 0; h < 2; h++) {
            int mi = wm * 64 + i * 16 + h * 8 + lr;
            int m  = m0 + mi;
            if (m >= Me) continue;
            int p = S->prow[mi];
            float g = (EPI == 1) ? d_gw[e * T_TOK + m] : 0.0f;
            #pragma unroll
            for (int j = 0; j < 4; j++) {
                int col = wn * 32 + j * 8 + 2 * lc;
                float v0 = acc[i][j][h * 2 + 0] + bias[col];
                float v1 = acc[i][j][h * 2 + 1] + bias[col + 1];
                if (EPI == 0) {
                    v0 = gelu_exact(v0); v1 = gelu_exact(v1);
                    size_t off = (size_t)p * DFF + n0 + col;
                    __nv_bfloat162 hh = __floats2bfloat162_rn(v0, v1);
                    float2 hf = __bfloat1622float2(hh);
                    __nv_bfloat162 ll = __floats2bfloat162_rn(v0 - hf.x, v1 - hf.y);
                    *(__nv_bfloat162*)(d_Hh + off) = hh;
                    *(__nv_bfloat162*)(d_Hl + off) = ll;
                } else {
                    float2 o = make_float2(g * v0, g * v1);
                    *(float2*)(d_Y + (size_t)p * DIM + n0 + col) = o;
                }
            }
        }
    }
}

// GEMM1: H[pair, DFF] = gelu( x[tok] @ w1[e]^T + b1[e] )
__global__ __launch_bounds__(256, 2) void ffn1_kernel(const float* __restrict__ b1)
{
    int e  = blockIdx.z;
    int Me = d_cnt[e];
    int m0 = blockIdx.y * BM;
    if (m0 >= Me) return;
    int n0 = blockIdx.x * BN;
    ffn_core<0, DIM>(d_xh, d_xl, DIM, true,
                     d_w1h + ((size_t)e * DFF + n0) * DIM,
                     d_w1l + ((size_t)e * DFF + n0) * DIM,
                     b1 + (size_t)e * DFF + n0,
                     e, Me, m0, n0);
}

// GEMM2: Y[pair, D] = gw * ( H[pair] @ w2[e]^T + b2[e] )
__global__ __launch_bounds__(256, 2) void ffn2_kernel(const float* __restrict__ b2)
{
    int e  = blockIdx.z;
    int Me = d_cnt[e];
    int m0 = blockIdx.y * BM;
    if (m0 >= Me) return;
    int n0 = blockIdx.x * BN;
    ffn_core<1, DFF>(d_Hh, d_Hl, DFF, false,
                     d_w2h + ((size_t)e * DIM + n0) * DFF,
                     d_w2l + ((size_t)e * DIM + n0) * DFF,
                     b2 + (size_t)e * DIM + n0,
                     e, Me, m0, n0);
}

// -------- combine two expert contributions per token --------
__global__ void combine_kernel(float* __restrict__ out)
{
    size_t i = (size_t)blockIdx.x * blockDim.x + threadIdx.x;
    size_t total = (size_t)T_TOK * DIM / 4;
    if (i >= total) return;
    size_t t = i / (DIM / 4);
    size_t d4 = i % (DIM / 4);
    const float4* y0 = (const float4*)(d_Y + (t * 2 + 0) * DIM) + d4;
    const float4* y1 = (const float4*)(d_Y + (t * 2 + 1) * DIM) + d4;
    float4 a = *y0, b = *y1;
    ((float4*)out)[i] = make_float4(a.x + b.x, a.y + b.y, a.z + b.z, a.w + b.w);
}

// -------- load-balance loss --------
__global__ void loss_kernel(float* __restrict__ out, int out_size)
{
    if (threadIdx.x == 0 && blockIdx.x == 0) {
        float lb = 0.0f;
        const float invT = 1.0f / (float)T_TOK;
        #pragma unroll
        for (int e = 0; e < NE; e++)
            lb += ((float)d_amax[e] * invT) * (d_probs[e] * invT);
        lb *= (float)NE;
        if (out_size > T_TOK * DIM) out[T_TOK * DIM] = lb;
    }
}

extern "C" void kernel_launch(void* const* d_in, const int* in_sizes, int n_in,
                              void* d_out, int out_size)
{
    const float* x      = (const float*)d_in[0];
    const float* gate_w = (const float*)d_in[1];
    const float* w1     = (const float*)d_in[2];
    const float* b1     = (const float*)d_in[3];
    const float* w2     = (const float*)d_in[4];
    const float* b2     = (const float*)d_in[5];
    float* out = (float*)d_out;

    cudaFuncSetAttribute(ffn1_kernel, cudaFuncAttributeMaxDynamicSharedMemorySize, SMEM_BYTES);
    cudaFuncSetAttribute(ffn2_kernel, cudaFuncAttributeMaxDynamicSharedMemorySize, SMEM_BYTES);

    zero_kernel<<<1, 32>>>();
    gate_kernel<<<T_TOK, 256>>>(x, gate_w);

    __nv_bfloat16 *xh, *xl, *w1h, *w1l, *w2h, *w2l;
    cudaGetSymbolAddress((void**)&xh,  d_xh);
    cudaGetSymbolAddress((void**)&xl,  d_xl);
    cudaGetSymbolAddress((void**)&w1h, d_w1h);
    cudaGetSymbolAddress((void**)&w1l, d_w1l);
    cudaGetSymbolAddress((void**)&w2h, d_w2h);
    cudaGetSymbolAddress((void**)&w2l, d_w2l);

    split_kernel<<<2048, 256>>>(x,  xh,  xl,  (size_t)T_TOK * DIM / 4);
    split_kernel<<<8192, 256>>>(w1, w1h, w1l, (size_t)NE * DFF * DIM / 4);
    split_kernel<<<8192, 256>>>(w2, w2h, w2l, (size_t)NE * DIM * DFF / 4);

    ffn1_kernel<<<dim3(DFF / BN, T_TOK / BM, NE), 256, SMEM_BYTES>>>(b1);
    ffn2_kernel<<<dim3(DIM / BN, T_TOK / BM, NE), 256, SMEM_BYTES>>>(b2);
    {
        size_t total = (size_t)T_TOK * DIM / 4;
        combine_kernel<<<(unsigned)((total + 255) / 256), 256>>>(out);
    }
    loss_kernel<<<1, 32>>>(out, out_size);
}

// round 11
// speedup vs baseline: 4.8316x; 1.0438x over previous
#include <cuda_runtime.h>
#include <cuda_bf16.h>
#include <math.h>
#include <stdint.h>

#define T_TOK 8192
#define DIM   1024
#define DFF   4096
#define NE    8

// -------- scratch (device globals; no allocation) --------
__device__ int   d_cnt[NE];
__device__ int   d_amax[NE];
__device__ float d_probs[NE];
__device__ int   d_tok[NE * T_TOK];   // pair id = t*2+slot
__device__ float d_gw [NE * T_TOK];
__device__ float d_Y[(size_t)2 * T_TOK * DIM];
// pre-split bf16 hi/lo operands
__device__ __nv_bfloat16 d_xh[(size_t)T_TOK * DIM];
__device__ __nv_bfloat16 d_xl[(size_t)T_TOK * DIM];
__device__ __nv_bfloat16 d_w1h[(size_t)NE * DFF * DIM];
__device__ __nv_bfloat16 d_w1l[(size_t)NE * DFF * DIM];
__device__ __nv_bfloat16 d_w2h[(size_t)NE * DIM * DFF];
__device__ __nv_bfloat16 d_w2l[(size_t)NE * DIM * DFF];
__device__ __nv_bfloat16 d_Hh[(size_t)2 * T_TOK * DFF];
__device__ __nv_bfloat16 d_Hl[(size_t)2 * T_TOK * DFF];

// -------- zero counters (graph replays) --------
__global__ void zero_kernel() {
    int i = threadIdx.x;
    if (i < NE) { d_cnt[i] = 0; d_amax[i] = 0; d_probs[i] = 0.0f; }
}

// -------- fp32 -> bf16 hi/lo split (grid-stride, float4) --------
__global__ __launch_bounds__(256) void split_kernel(
    const float* __restrict__ src, __nv_bfloat16* __restrict__ hi,
    __nv_bfloat16* __restrict__ lo, size_t n4)
{
    for (size_t i = (size_t)blockIdx.x * blockDim.x + threadIdx.x; i < n4;
         i += (size_t)gridDim.x * blockDim.x) {
        float4 v = ((const float4*)src)[i];
        __nv_bfloat162 h0 = __floats2bfloat162_rn(v.x, v.y);
        __nv_bfloat162 h1 = __floats2bfloat162_rn(v.z, v.w);
        float2 f0 = __bfloat1622float2(h0);
        float2 f1 = __bfloat1622float2(h1);
        __nv_bfloat162 l0 = __floats2bfloat162_rn(v.x - f0.x, v.y - f0.y);
        __nv_bfloat162 l1 = __floats2bfloat162_rn(v.z - f1.x, v.w - f1.y);
        ((__nv_bfloat162*)hi)[2 * i]     = h0;
        ((__nv_bfloat162*)hi)[2 * i + 1] = h1;
        ((__nv_bfloat162*)lo)[2 * i]     = l0;
        ((__nv_bfloat162*)lo)[2 * i + 1] = l1;
    }
}

// -------- gating --------
__global__ __launch_bounds__(256) void gate_kernel(
    const float* __restrict__ x, const float* __restrict__ gate_w)
{
    int t = blockIdx.x;
    __shared__ float xs[DIM];
    __shared__ float lg[NE];
    for (int i = threadIdx.x; i < DIM; i += 256) xs[i] = x[(size_t)t * DIM + i];
    __syncthreads();
    int w = threadIdx.x >> 5, lane = threadIdx.x & 31;
    const float* gr = gate_w + w * DIM;
    float s = 0.0f;
    for (int i = lane; i < DIM; i += 32) s += xs[i] * gr[i];
    #pragma unroll
    for (int o = 16; o; o >>= 1) s += __shfl_xor_sync(0xffffffffu, s, o);
    if (lane == 0) lg[w] = s;
    __syncthreads();
    if (threadIdx.x == 0) {
        int i0 = 0;
        #pragma unroll
        for (int e = 1; e < NE; e++) if (lg[e] > lg[i0]) i0 = e;
        int i1 = -1;
        #pragma unroll
        for (int e = 0; e < NE; e++) {
            if (e == i0) continue;
            if (i1 < 0 || lg[e] > lg[i1]) i1 = e;
        }
        float v0 = lg[i0], v1 = lg[i1];
        float ee = expf(v1 - v0);
        float g0 = 1.0f / (1.0f + ee);
        float g1 = ee / (1.0f + ee);
        float mx = v0, se = 0.0f, p[NE];
        #pragma unroll
        for (int e = 0; e < NE; e++) { p[e] = expf(lg[e] - mx); se += p[e]; }
        float inv = 1.0f / se;
        #pragma unroll
        for (int e = 0; e < NE; e++) atomicAdd(&d_probs[e], p[e] * inv);
        atomicAdd(&d_amax[i0], 1);
        int pos0 = atomicAdd(&d_cnt[i0], 1);
        d_tok[i0 * T_TOK + pos0] = t * 2 + 0;
        d_gw [i0 * T_TOK + pos0] = g0;
        int pos1 = atomicAdd(&d_cnt[i1], 1);
        d_tok[i1 * T_TOK + pos1] = t * 2 + 1;
        d_gw [i1 * T_TOK + pos1] = g1;
    }
}

__device__ __forceinline__ float gelu_exact(float v) {
    return 0.5f * v * (1.0f + erff(v * 0.7071067811865475f));
}

// ====== bf16 hi/lo (3xMMA) gather-GEMM: ldmatrix, asymmetric cp.async =====
// BM=BN=128, BK=32, 256 thr (8 warps 2x4), warp tile 64x32, m16n8k16.
// A (activations, mostly L2): 2 stages.  B (weights, DRAM): 3 stages.
// smem row stride 40 bf16 (80B): 16B-aligned rows, LDSM conflict-free.

#define BM 128
#define BN 128
#define BK 32
#define ASTG 2
#define BSTG 3
#define SST 40                      // smem row stride in bf16
#define ROWB (SST * 2)              // 80 bytes per row

struct SmemT {
    __nv_bfloat16 Ah[ASTG][BM][SST];
    __nv_bfloat16 Al[ASTG][BM][SST];
    __nv_bfloat16 Bh[BSTG][BN][SST];
    __nv_bfloat16 Bl[BSTG][BN][SST];
    int prow[BM];
};
#define SMEM_BYTES sizeof(SmemT)

__device__ __forceinline__ uint32_t smem_u32(const void* p) {
    return (uint32_t)__cvta_generic_to_shared(p);
}
__device__ __forceinline__ void cp16(uint32_t dst, const void* src, int src_bytes) {
    asm volatile("cp.async.cg.shared.global [%0], [%1], 16, %2;"
                 :: "r"(dst), "l"(src), "r"(src_bytes) : "memory");
}
__device__ __forceinline__ void cp_commit() {
    asm volatile("cp.async.commit_group;" ::: "memory");
}
template<int N> __device__ __forceinline__ void cp_wait() {
    asm volatile("cp.async.wait_group %0;" :: "n"(N) : "memory");
}
__device__ __forceinline__ void mma16(float* c, const uint32_t* a, const uint32_t* b) {
    asm volatile(
        "mma.sync.aligned.m16n8k16.row.col.f32.bf16.bf16.f32 "
        "{%0,%1,%2,%3}, {%4,%5,%6,%7}, {%8,%9}, {%0,%1,%2,%3};"
        : "+f"(c[0]), "+f"(c[1]), "+f"(c[2]), "+f"(c[3])
        : "r"(a[0]), "r"(a[1]), "r"(a[2]), "r"(a[3]), "r"(b[0]), "r"(b[1]));
}
__device__ __forceinline__ void ldsm4(uint32_t* r, uint32_t addr) {
    asm volatile("ldmatrix.sync.aligned.m8n8.x4.shared.b16 {%0,%1,%2,%3}, [%4];"
                 : "=r"(r[0]), "=r"(r[1]), "=r"(r[2]), "=r"(r[3]) : "r"(addr));
}

// EPI=0: gelu(acc+bias) -> Hh/Hl ; EPI=1: g*(acc+bias) -> d_Y
template<int EPI, int KDIM>
__device__ __forceinline__ void ffn_core(
    const __nv_bfloat16* __restrict__ Ah, const __nv_bfloat16* __restrict__ Al,
    size_t Astride, bool Agather,
    const __nv_bfloat16* __restrict__ Bh, const __nv_bfloat16* __restrict__ Bl,
    const float* __restrict__ bias,       // offset to (e, n0)
    int e, int Me, int m0, int n0)
{
    extern __shared__ char smem_raw[];
    SmemT* S = (SmemT*)smem_raw;
    int tid = threadIdx.x;

    if (tid < BM) S->prow[tid] = (m0 + tid < Me) ? d_tok[e * T_TOK + m0 + tid] : -1;
    __syncthreads();

    // loader: row = tid>>1, two 16B chunks (8 bf16 each) at (tid&1)*16
    int lrow = tid >> 1;
    int lcb  = (tid & 1) * 16;
    int pa = S->prow[lrow];
    size_t arow = (pa >= 0) ? (Agather ? (size_t)(pa >> 1) : (size_t)pa) * Astride : 0;
    int asz = (pa >= 0) ? 16 : 0;
    const __nv_bfloat16* agh = Ah + arow + lcb;
    const __nv_bfloat16* agl = Al + arow + lcb;
    const __nv_bfloat16* bgh = Bh + (size_t)lrow * KDIM + lcb;
    const __nv_bfloat16* bgl = Bl + (size_t)lrow * KDIM + lcb;

    const int NT = KDIM / BK;

    // issue helpers (each = one commit group of 4 cp.async)
    auto issueA = [&](int t, int s) {
        int ko = t * BK;
        #pragma unroll
        for (int q = 0; q < 2; q++) {
            cp16(smem_u32(&S->Ah[s][lrow][lcb + q * 8]), agh + ko + q * 8, asz);
            cp16(smem_u32(&S->Al[s][lrow][lcb + q * 8]), agl + ko + q * 8, asz);
        }
        cp_commit();
    };
    auto issueB = [&](int t, int s) {
        int ko = t * BK;
        #pragma unroll
        for (int q = 0; q < 2; q++) {
            cp16(smem_u32(&S->Bh[s][lrow][lcb + q * 8]), bgh + ko + q * 8, 16);
            cp16(smem_u32(&S->Bl[s][lrow][lcb + q * 8]), bgl + ko + q * 8, 16);
        }
        cp_commit();
    };

    // prologue: [A0][B0][B1]
    issueA(0, 0);
    issueB(0, 0);
    issueB(1, 1);

    int wid = tid >> 5, lane = tid & 31;
    int wm = wid >> 2, wn = wid & 3;
    int lr = lane >> 2, lc = lane & 3;

    // ldmatrix lane->address mapping (per-stage bases)
    int aRow = wm * 64 + (lane & 7) + ((lane >> 3) & 1) * 8;
    int aK   = (lane >> 4) * 8;
    int bMat = lane >> 3;
    int bRow = wn * 32 + (bMat >> 1) * 8 + (lane & 7);
    int bK   = (bMat & 1) * 8;
    uint32_t aBH[ASTG], aBL[ASTG], bBH[BSTG], bBL[BSTG];
    #pragma unroll
    for (int b = 0; b < ASTG; b++) {
        aBH[b] = smem_u32(&S->Ah[b][aRow][aK]);
        aBL[b] = smem_u32(&S->Al[b][aRow][aK]);
    }
    #pragma unroll
    for (int b = 0; b < BSTG; b++) {
        bBH[b] = smem_u32(&S->Bh[b][bRow][bK]);
        bBL[b] = smem_u32(&S->Bl[b][bRow][bK]);
    }

    float acc[4][4][4] = {};

    cp_wait<1>();          // A0,B0 done; B1 may fly
    __syncthreads();

    int ca = 0, cb = 0;
    for (int kt = 0; kt < NT; kt++) {
        bool has_a = (kt + 1 < NT);
        bool has_b = (kt + 2 < NT);
        // commit order per iter: [A(kt+1)] then [B(kt+2)]
        if (has_a) issueA(kt + 1, ca ^ 1);
        if (has_b) issueB(kt + 2, (cb + 2 >= BSTG) ? cb + 2 - BSTG : cb + 2);

        #pragma unroll
        for (int kk = 0; kk < BK; kk += 16) {
            uint32_t bh[2][4], bl[2][4];
            ldsm4(bh[0], bBH[cb] + kk * 2);
            ldsm4(bh[1], bBH[cb] + 16 * ROWB + kk * 2);
            ldsm4(bl[0], bBL[cb] + kk * 2);
            ldsm4(bl[1], bBL[cb] + 16 * ROWB + kk * 2);
            #pragma unroll
            for (int i = 0; i < 4; i++) {
                uint32_t ah[4], al[4];
                ldsm4(ah, aBH[ca] + i * 16 * ROWB + kk * 2);
                ldsm4(al, aBL[ca] + i * 16 * ROWB + kk * 2);
                #pragma unroll
                for (int j = 0; j < 4; j++) {
                    const uint32_t* bhp = &bh[j >> 1][(j & 1) * 2];
                    const uint32_t* blp = &bl[j >> 1][(j & 1) * 2];
                    mma16(acc[i][j], ah, bhp);
                    mma16(acc[i][j], ah, blp);
                    mma16(acc[i][j], al, bhp);
                }
            }
        }

        if (has_a) {
            // need A(kt+1) and B(kt+1) complete before next compute.
            // tail-pending after this wait: only B(kt+2) when present.
            if (has_b) cp_wait<1>(); else cp_wait<0>();
            __syncthreads();
        }
        ca ^= 1;
        cb = (cb + 1 == BSTG) ? 0 : cb + 1;
    }

    // epilogue
    #pragma unroll
    for (int i = 0; i < 4; i++) {
        #pragma unroll
        for (int h = 0; h < 2; h++) {
            int mi = wm * 64 + i * 16 + h * 8 + lr;
            int m  = m0 + mi;
            if (m >= Me) continue;
            int p = S->prow[mi];
            float g = (EPI == 1) ? d_gw[e * T_TOK + m] : 0.0f;
            #pragma unroll
            for (int j = 0; j < 4; j++) {
                int col = wn * 32 + j * 8 + 2 * lc;
                float v0 = acc[i][j][h * 2 + 0] + bias[col];
                float v1 = acc[i][j][h * 2 + 1] + bias[col + 1];
                if (EPI == 0) {
                    v0 = gelu_exact(v0); v1 = gelu_exact(v1);
                    size_t off = (size_t)p * DFF + n0 + col;
                    __nv_bfloat162 hh = __floats2bfloat162_rn(v0, v1);
                    float2 hf = __bfloat1622float2(hh);
                    __nv_bfloat162 ll = __floats2bfloat162_rn(v0 - hf.x, v1 - hf.y);
                    *(__nv_bfloat162*)(d_Hh + off) = hh;
                    *(__nv_bfloat162*)(d_Hl + off) = ll;
                } else {
                    float2 o = make_float2(g * v0, g * v1);
                    *(float2*)(d_Y + (size_t)p * DIM + n0 + col) = o;
                }
            }
        }
    }
}

// GEMM1: H[pair, DFF] = gelu( x[tok] @ w1[e]^T + b1[e] )
__global__ __launch_bounds__(256, 2) void ffn1_kernel(const float* __restrict__ b1)
{
    int e  = blockIdx.z;
    int Me = d_cnt[e];
    int m0 = blockIdx.y * BM;
    if (m0 >= Me) return;
    int n0 = blockIdx.x * BN;
    ffn_core<0, DIM>(d_xh, d_xl, DIM, true,
                     d_w1h + ((size_t)e * DFF + n0) * DIM,
                     d_w1l + ((size_t)e * DFF + n0) * DIM,
                     b1 + (size_t)e * DFF + n0,
                     e, Me, m0, n0);
}

// GEMM2: Y[pair, D] = gw * ( H[pair] @ w2[e]^T + b2[e] )
__global__ __launch_bounds__(256, 2) void ffn2_kernel(const float* __restrict__ b2)
{
    int e  = blockIdx.z;
    int Me = d_cnt[e];
    int m0 = blockIdx.y * BM;
    if (m0 >= Me) return;
    int n0 = blockIdx.x * BN;
    ffn_core<1, DFF>(d_Hh, d_Hl, DFF, false,
                     d_w2h + ((size_t)e * DIM + n0) * DFF,
                     d_w2l + ((size_t)e * DIM + n0) * DFF,
                     b2 + (size_t)e * DIM + n0,
                     e, Me, m0, n0);
}

// -------- combine two expert contributions per token --------
__global__ void combine_kernel(float* __restrict__ out)
{
    size_t i = (size_t)blockIdx.x * blockDim.x + threadIdx.x;
    size_t total = (size_t)T_TOK * DIM / 4;
    if (i >= total) return;
    size_t t = i / (DIM / 4);
    size_t d4 = i % (DIM / 4);
    const float4* y0 = (const float4*)(d_Y + (t * 2 + 0) * DIM) + d4;
    const float4* y1 = (const float4*)(d_Y + (t * 2 + 1) * DIM) + d4;
    float4 a = *y0, b = *y1;
    ((float4*)out)[i] = make_float4(a.x + b.x, a.y + b.y, a.z + b.z, a.w + b.w);
}

// -------- load-balance loss --------
__global__ void loss_kernel(float* __restrict__ out, int out_size)
{
    if (threadIdx.x == 0 && blockIdx.x == 0) {
        float lb = 0.0f;
        const float invT = 1.0f / (float)T_TOK;
        #pragma unroll
        for (int e = 0; e < NE; e++)
            lb += ((float)d_amax[e] * invT) * (d_probs[e] * invT);
        lb *= (float)NE;
        if (out_size > T_TOK * DIM) out[T_TOK * DIM] = lb;
    }
}

extern "C" void kernel_launch(void* const* d_in, const int* in_sizes, int n_in,
                              void* d_out, int out_size)
{
    const float* x      = (const float*)d_in[0];
    const float* gate_w = (const float*)d_in[1];
    const float* w1     = (const float*)d_in[2];
    const float* b1     = (const float*)d_in[3];
    const float* w2     = (const float*)d_in[4];
    const float* b2     = (const float*)d_in[5];
    float* out = (float*)d_out;

    cudaFuncSetAttribute(ffn1_kernel, cudaFuncAttributeMaxDynamicSharedMemorySize, SMEM_BYTES);
    cudaFuncSetAttribute(ffn2_kernel, cudaFuncAttributeMaxDynamicSharedMemorySize, SMEM_BYTES);

    zero_kernel<<<1, 32>>>();
    gate_kernel<<<T_TOK, 256>>>(x, gate_w);

    __nv_bfloat16 *xh, *xl, *w1h, *w1l, *w2h, *w2l;
    cudaGetSymbolAddress((void**)&xh,  d_xh);
    cudaGetSymbolAddress((void**)&xl,  d_xl);
    cudaGetSymbolAddress((void**)&w1h, d_w1h);
    cudaGetSymbolAddress((void**)&w1l, d_w1l);
    cudaGetSymbolAddress((void**)&w2h, d_w2h);
    cudaGetSymbolAddress((void**)&w2l, d_w2l);

    split_kernel<<<2048, 256>>>(x,  xh,  xl,  (size_t)T_TOK * DIM / 4);
    split_kernel<<<8192, 256>>>(w1, w1h, w1l, (size_t)NE * DFF * DIM / 4);
    split_kernel<<<8192, 256>>>(w2, w2h, w2l, (size_t)NE * DIM * DFF / 4);

    ffn1_kernel<<<dim3(DFF / BN, T_TOK / BM, NE), 256, SMEM_BYTES>>>(b1);
    ffn2_kernel<<<dim3(DIM / BN, T_TOK / BM, NE), 256, SMEM_BYTES>>>(b2);
    {
        size_t total = (size_t)T_TOK * DIM / 4;
        combine_kernel<<<(unsigned)((total + 255) / 256), 256>>>(out);
    }
    loss_kernel<<<1, 32>>>(out, out_size);
}